// round 1
// baseline (speedup 1.0000x reference)
#include <cuda_runtime.h>
#include <math.h>

#define NODES 4
#define CCH 256
#define PCH 64
#define NB 64
#define HWD 32
#define PLANE (HWD*HWD)          // 1024
#define EDGES 10
#define STATE_ELEMS ((size_t)NB*CCH*PLANE)   // 16,777,216

// ---------------- device scratch (no allocations allowed) ----------------
__device__ float g_w[EDGES][12];
// merged 9x9 weights, layout [e][ci][tap(81)][o(64)] as float4 groups of 16 per tap
__device__ float4 g_Weff[EDGES][PCH][81*16];
// intermediate node outputs (states[1..3]); final node writes d_out directly
__device__ float g_state[3][NB*CCH*PLANE];

__constant__ int c_edge_node[EDGES] = {0,1,1,2,2,2,3,3,3,3};
__constant__ int c_edge_i[EDGES]    = {0,0,1,0,1,2,0,1,2,3};

// ---------------- packed f32x2 helpers ----------------
__device__ __forceinline__ unsigned long long pack2(float a, float b){
    unsigned long long r;
    asm("mov.b64 %0, {%1, %2};" : "=l"(r) : "f"(a), "f"(b));
    return r;
}
__device__ __forceinline__ void fma2(unsigned long long &d, unsigned long long a, unsigned long long b){
    asm("fma.rn.f32x2 %0, %1, %2, %0;" : "+l"(d) : "l"(a), "l"(b));
}
__device__ __forceinline__ float2 unpack2(unsigned long long v){
    float2 f;
    asm("mov.b64 {%0, %1}, %2;" : "=f"(f.x), "=f"(f.y) : "l"(v));
    return f;
}

// ---------------- kernel 1: edge softmax weights ----------------
__global__ void k_softmax(const float* __restrict__ arch, const float* __restrict__ norms){
    int e = threadIdx.x;
    if (e >= EDGES) return;
    int node = c_edge_node[e], i = c_edge_i[e];
    float nrm = norms[node*(NODES+1)+i];
    nrm = fmaxf(nrm, 1e-5f);   // jnp.clip(x, 1e-5) lower bound; STRENGTH=1
    const float* a = arch + (size_t)(node*(NODES+1)+i)*12;
    float l[12], mx = -1e30f;
    #pragma unroll
    for (int k = 0; k < 12; k++){ l[k] = a[k] / nrm; mx = fmaxf(mx, l[k]); }
    float s = 0.f;
    #pragma unroll
    for (int k = 0; k < 12; k++){ l[k] = expf(l[k] - mx); s += l[k]; }
    float inv = 1.f / s;
    #pragma unroll
    for (int k = 0; k < 12; k++) g_w[e][k] = l[k] * inv;
}

// ---------------- kernel 2: merge all linear ops into one 9x9 dense conv ----------------
// out tap offset dy,dx in [-4,4]; lax.conv is cross-correlation (no flip):
//   tap offset = k*dil - pad  for each source kernel
__global__ void k_merge(const float* __restrict__ w3c,  const float* __restrict__ w5c,
                        const float* __restrict__ w7c,  const float* __restrict__ w1c,
                        const float* __restrict__ s3dw, const float* __restrict__ s3pw,
                        const float* __restrict__ s5dw, const float* __restrict__ s5pw,
                        const float* __restrict__ d3c,  const float* __restrict__ d5c){
    long long t = (long long)blockIdx.x * blockDim.x + threadIdx.x;
    const long long TOT = (long long)EDGES * PCH * 81 * PCH;
    if (t >= TOT) return;
    int o  = (int)(t & 63);
    int kk = (int)((t >> 6) % 81);
    int i  = (int)(((t >> 6) / 81) % 64);
    int e  = (int)(t / (64LL*81*64));
    int ky = kk / 9, kx = kk % 9;
    int dy = ky - 4, dx = kx - 4;
    int ady = dy < 0 ? -dy : dy;
    int adx = dx < 0 ? -dx : dx;
    const float* w = g_w[e];
    long long oi = ((long long)e*64 + o)*64 + i;
    long long ei = (long long)e*64 + i;
    float val = 0.f;
    if (ady <= 3 && adx <= 3)
        val += w[3] * w7c[oi*49 + (dy+3)*7 + (dx+3)];
    if (ady <= 2 && adx <= 2){
        val += w[2] * w5c[oi*25 + (dy+2)*5 + (dx+2)];
        val += w[8] * s5pw[oi] * s5dw[ei*25 + (dy+2)*5 + (dx+2)];
    }
    if (ady <= 1 && adx <= 1){
        val += w[1] * w3c[oi*9 + (dy+1)*3 + (dx+1)];
        val += w[7] * s3pw[oi] * s3dw[ei*9 + (dy+1)*3 + (dx+1)];
    }
    if (dy == 0 && dx == 0){
        val += w[4] * w1c[oi];
        if (o == i) val += w[0];   // identity branch
    }
    if (((dy & 1) == 0) && ((dx & 1) == 0)){
        if (ady <= 2 && adx <= 2)
            val += w[9] * d3c[oi*9 + (dy/2+1)*3 + (dx/2+1)];
        val += w[10] * d5c[oi*25 + (dy/2+2)*5 + (dx/2+2)];
    }
    // store layout [e][i][tap][o]  (o contiguous for vectorized smem loads)
    float* wf = (float*)g_Weff;
    wf[ (((long long)e*64 + i)*81 + kk)*64 + o ] = val;
}

// ---------------- kernel 3: max/avg 3x3 pooling accumulate (full 256 channels) ----------------
template<bool INIT>
__global__ void k_pool(const float* __restrict__ xin, float* __restrict__ dout,
                       int e, int src_sel, int dst_sel){
    const float* src = (src_sel == 0) ? xin : g_state[src_sel - 1];
    float* dst = (dst_sel == 3) ? dout : g_state[dst_sel];
    size_t base = (size_t)blockIdx.x * PLANE;
    __shared__ float tile[PLANE];
    for (int t = threadIdx.x; t < PLANE; t += 256) tile[t] = src[base + t];
    float w5v = g_w[e][5], w6v = g_w[e][6];
    __syncthreads();
    #pragma unroll
    for (int q = 0; q < 4; q++){
        int p = threadIdx.x + q*256;
        int y = p >> 5, x = p & 31;
        float m = -INFINITY, s = 0.f;
        #pragma unroll
        for (int dy = -1; dy <= 1; dy++){
            int yy = y + dy;
            if (yy < 0 || yy >= HWD) continue;
            #pragma unroll
            for (int dx = -1; dx <= 1; dx++){
                int xx = x + dx;
                if (xx < 0 || xx >= HWD) continue;
                float v = tile[yy*HWD + xx];
                m = fmaxf(m, v);
                s += v;
            }
        }
        float r = w5v*m + w6v*(s * (1.f/9.f));
        if (INIT) dst[base + p] = r;
        else      dst[base + p] += r;
    }
}

// ---------------- kernel 4: dense merged 9x9 conv over gathered channels ----------------
// block: (tile 32x8 of one image n) ; thread = one output pixel ; 64 out-ch accumulators (32 f32x2)
__global__ __launch_bounds__(256, 2)
void k_conv(const float* __restrict__ xin, float* __restrict__ dout,
            const int* __restrict__ idx_all, int e, int src_sel, int dst_sel){
    const float* src = (src_sel == 0) ? xin : g_state[src_sel - 1];
    float* dst = (dst_sel == 3) ? dout : g_state[dst_sel];
    const int* ids = idx_all + e*64;

    int n  = blockIdx.y;
    int y0 = blockIdx.x * 8;
    int tid = threadIdx.x;
    int tx = tid & 31, ty = tid >> 5;

    __shared__ float4 w_s[81*16];      // weights for current ci: [tap][o/4]
    __shared__ float  in_s[16*40];     // input halo tile: rows y0-4..y0+11, cols -4..35
    __shared__ int    ids_s[64];
    if (tid < 64) ids_s[tid] = ids[tid];

    unsigned long long acc[32];
    #pragma unroll
    for (int j = 0; j < 32; j++) acc[j] = 0ULL;

    for (int ci = 0; ci < 64; ci++){
        __syncthreads();
        const float4* wg = g_Weff[e][ci];
        #pragma unroll
        for (int t = 0; t < 6; t++){
            int u = tid + t*256;
            if (u < 81*16) w_s[u] = wg[u];
        }
        const float* sp = src + ((size_t)n*CCH + ids_s[ci]) * PLANE;
        #pragma unroll
        for (int t = 0; t < 3; t++){
            int u = tid + t*256;
            if (u < 640){
                int rr = u / 40, cc = u % 40;
                int r = y0 - 4 + rr, col = cc - 4;
                float v = 0.f;
                if (r >= 0 && r < HWD && col >= 0 && col < HWD) v = sp[r*HWD + col];
                in_s[u] = v;
            }
        }
        __syncthreads();

        #pragma unroll 1
        for (int ky = 0; ky < 9; ky++){
            const float* inrow = &in_s[(ty + ky)*40 + tx];
            #pragma unroll 1
            for (int kx = 0; kx < 9; kx++){
                float v = inrow[kx];
                unsigned long long vv = pack2(v, v);
                const ulonglong2* wp = (const ulonglong2*)&w_s[(ky*9 + kx)*16];
                #pragma unroll
                for (int j = 0; j < 16; j++){
                    ulonglong2 ww = wp[j];
                    fma2(acc[2*j],   ww.x, vv);
                    fma2(acc[2*j+1], ww.y, vv);
                }
            }
        }
    }

    // scatter-add into acc buffer at the gathered channel positions
    int y = y0 + ty;
    size_t obase = (size_t)n*CCH*PLANE + (size_t)y*HWD + tx;
    #pragma unroll
    for (int j = 0; j < 32; j++){
        float2 f = unpack2(acc[j]);
        dst[obase + (size_t)ids_s[2*j]  *PLANE] += f.x;
        dst[obase + (size_t)ids_s[2*j+1]*PLANE] += f.y;
    }
}

// ---------------- launch ----------------
extern "C" void kernel_launch(void* const* d_in, const int* in_sizes, int n_in,
                              void* d_out, int out_size){
    const float* x     = (const float*)d_in[0];
    const float* arch  = (const float*)d_in[1];
    const float* norms = (const float*)d_in[2];
    const int*   idx   = (const int*)  d_in[3];
    const float* w3c   = (const float*)d_in[4];
    const float* w5c   = (const float*)d_in[5];
    const float* w7c   = (const float*)d_in[6];
    const float* w1c   = (const float*)d_in[7];
    const float* s3dw  = (const float*)d_in[8];
    const float* s3pw  = (const float*)d_in[9];
    const float* s5dw  = (const float*)d_in[10];
    const float* s5pw  = (const float*)d_in[11];
    const float* d3c   = (const float*)d_in[12];
    const float* d5c   = (const float*)d_in[13];
    float* out = (float*)d_out;

    k_softmax<<<1, 32>>>(arch, norms);

    long long TOT = (long long)EDGES * PCH * 81 * PCH;
    int mb = (int)((TOT + 255) / 256);
    k_merge<<<mb, 256>>>(w3c, w5c, w7c, w1c, s3dw, s3pw, s5dw, s5pw, d3c, d5c);

    int e = 0;
    for (int node = 0; node < NODES; node++){
        for (int i = 0; i <= node; i++){
            if (i == 0) k_pool<true ><<<NB*CCH, 256>>>(x, out, e, i, node);
            else        k_pool<false><<<NB*CCH, 256>>>(x, out, e, i, node);
            k_conv<<<dim3(4, NB), 256>>>(x, out, idx, e, i, node);
            e++;
        }
    }
}

// round 4
// speedup vs baseline: 1.3423x; 1.3423x over previous
#include <cuda_runtime.h>
#include <math.h>

#define NODES 4
#define CCH 256
#define PCH 64
#define NB 64
#define HWD 32
#define PLANE (HWD*HWD)          // 1024
#define EDGES 10

// ---------------- device scratch (no allocations allowed) ----------------
__device__ float g_w[EDGES][12];
// merged 9x9 weights, layout [e][ci][tap(81)][o(64)]
__device__ float4 g_Weff[EDGES][PCH][81*16];
// intermediate node outputs (states[1..3]); final node writes d_out directly
__device__ float g_state[3][NB*CCH*PLANE];

__constant__ int c_edge_node[EDGES] = {0,1,1,2,2,2,3,3,3,3};
__constant__ int c_edge_i[EDGES]    = {0,0,1,0,1,2,0,1,2,3};

// ---------------- packed f32x2 helpers ----------------
__device__ __forceinline__ unsigned long long pack2(float a, float b){
    unsigned long long r;
    asm("mov.b64 %0, {%1, %2};" : "=l"(r) : "f"(a), "f"(b));
    return r;
}
__device__ __forceinline__ void fma2(unsigned long long &d, unsigned long long a, unsigned long long b){
    asm("fma.rn.f32x2 %0, %1, %2, %0;" : "+l"(d) : "l"(a), "l"(b));
}
__device__ __forceinline__ float2 unpack2(unsigned long long v){
    float2 f;
    asm("mov.b64 {%0, %1}, %2;" : "=f"(f.x), "=f"(f.y) : "l"(v));
    return f;
}

// ---------------- kernel 1: edge softmax weights ----------------
__global__ void k_softmax(const float* __restrict__ arch, const float* __restrict__ norms){
    int e = threadIdx.x;
    if (e >= EDGES) return;
    int node = c_edge_node[e], i = c_edge_i[e];
    float nrm = norms[node*(NODES+1)+i];
    nrm = fmaxf(nrm, 1e-5f);
    const float* a = arch + (size_t)(node*(NODES+1)+i)*12;
    float l[12], mx = -1e30f;
    #pragma unroll
    for (int k = 0; k < 12; k++){ l[k] = a[k] / nrm; mx = fmaxf(mx, l[k]); }
    float s = 0.f;
    #pragma unroll
    for (int k = 0; k < 12; k++){ l[k] = expf(l[k] - mx); s += l[k]; }
    float inv = 1.f / s;
    #pragma unroll
    for (int k = 0; k < 12; k++) g_w[e][k] = l[k] * inv;
}

// ---------------- kernel 2: merge all linear ops into one 9x9 dense conv ----------------
__global__ void k_merge(const float* __restrict__ w3c,  const float* __restrict__ w5c,
                        const float* __restrict__ w7c,  const float* __restrict__ w1c,
                        const float* __restrict__ s3dw, const float* __restrict__ s3pw,
                        const float* __restrict__ s5dw, const float* __restrict__ s5pw,
                        const float* __restrict__ d3c,  const float* __restrict__ d5c){
    long long t = (long long)blockIdx.x * blockDim.x + threadIdx.x;
    const long long TOT = (long long)EDGES * PCH * 81 * PCH;
    if (t >= TOT) return;
    int o  = (int)(t & 63);
    int kk = (int)((t >> 6) % 81);
    int i  = (int)(((t >> 6) / 81) % 64);
    int e  = (int)(t / (64LL*81*64));
    int ky = kk / 9, kx = kk % 9;
    int dy = ky - 4, dx = kx - 4;
    int ady = dy < 0 ? -dy : dy;
    int adx = dx < 0 ? -dx : dx;
    const float* w = g_w[e];
    long long oi = ((long long)e*64 + o)*64 + i;
    long long ei = (long long)e*64 + i;
    float val = 0.f;
    if (ady <= 3 && adx <= 3)
        val += w[3] * w7c[oi*49 + (dy+3)*7 + (dx+3)];
    if (ady <= 2 && adx <= 2){
        val += w[2] * w5c[oi*25 + (dy+2)*5 + (dx+2)];
        val += w[8] * s5pw[oi] * s5dw[ei*25 + (dy+2)*5 + (dx+2)];
    }
    if (ady <= 1 && adx <= 1){
        val += w[1] * w3c[oi*9 + (dy+1)*3 + (dx+1)];
        val += w[7] * s3pw[oi] * s3dw[ei*9 + (dy+1)*3 + (dx+1)];
    }
    if (dy == 0 && dx == 0){
        val += w[4] * w1c[oi];
        if (o == i) val += w[0];
    }
    if (((dy & 1) == 0) && ((dx & 1) == 0)){
        if (ady <= 2 && adx <= 2)
            val += w[9] * d3c[oi*9 + (dy/2+1)*3 + (dx/2+1)];
        val += w[10] * d5c[oi*25 + (dy/2+2)*5 + (dx/2+2)];
    }
    float* wf = (float*)g_Weff;
    wf[ (((long long)e*64 + i)*81 + kk)*64 + o ] = val;
}

// ---------------- kernel 3: max/avg 3x3 pooling accumulate (full 256 channels) ----------------
template<bool INIT>
__global__ void k_pool(const float* __restrict__ xin, float* __restrict__ dout,
                       int e, int src_sel, int dst_sel){
    const float* src = (src_sel == 0) ? xin : g_state[src_sel - 1];
    float* dst = (dst_sel == 3) ? dout : g_state[dst_sel];
    size_t base = (size_t)blockIdx.x * PLANE;
    __shared__ float tile[PLANE];
    for (int t = threadIdx.x; t < PLANE; t += 256) tile[t] = src[base + t];
    float w5v = g_w[e][5], w6v = g_w[e][6];
    __syncthreads();
    #pragma unroll
    for (int q = 0; q < 4; q++){
        int p = threadIdx.x + q*256;
        int y = p >> 5, x = p & 31;
        float m = -INFINITY, s = 0.f;
        #pragma unroll
        for (int dy = -1; dy <= 1; dy++){
            int yy = y + dy;
            if (yy < 0 || yy >= HWD) continue;
            #pragma unroll
            for (int dx = -1; dx <= 1; dx++){
                int xx = x + dx;
                if (xx < 0 || xx >= HWD) continue;
                float v = tile[yy*HWD + xx];
                m = fmaxf(m, v);
                s += v;
            }
        }
        float r = w5v*m + w6v*(s * (1.f/9.f));
        if (INIT) dst[base + p] = r;
        else      dst[base + p] += r;
    }
}

// ---------------- kernel 4: dense merged 9x9 conv, register-tiled 8oc x 8px ----------------
// block = 8x32 output tile of one image. warp = one oc-group of 8 channels.
// lane = output column x; thread accumulates 8 rows x 8 oc = 32 f32x2 regs.
// kx is a RUNTIME loop (small code footprint, fits L0 I$); ky fully unrolled.
// Zero taps of the merged 9x9 (16 of 81) are skipped via uniform runtime
// branches on kx parity/range, which factor exactly per compile-time ky:
//   ky in {0,8}  -> active iff kx even
//   ky odd       -> active iff 1<=kx<=7
//   ky in {2,4,6}-> always active
__global__ __launch_bounds__(256)
void k_conv(const float* __restrict__ xin, float* __restrict__ dout,
            const int* __restrict__ idx_all, int e, int src_sel, int dst_sel){
    const float* src = (src_sel == 0) ? xin : g_state[src_sel - 1];
    float* dst = (dst_sel == 3) ? dout : g_state[dst_sel];
    const int* ids = idx_all + e*64;

    int n   = blockIdx.y;
    int y0  = blockIdx.x * 8;
    int tid = threadIdx.x;
    int lane = tid & 31;   // output column x
    int og   = tid >> 5;   // oc group (warp id): oc = og*8 .. og*8+7

    __shared__ float w_s[81*64];     // weights for current ci: [tap][o]
    __shared__ float in_s[16*40];    // halo tile rows y0-4..y0+11, cols -4..35
    __shared__ int   ids_s[64];
    if (tid < 64) ids_s[tid] = ids[tid];

    unsigned long long acc[32];      // [ocpair(4)][row(8)]
    #pragma unroll
    for (int j = 0; j < 32; j++) acc[j] = 0ULL;

    for (int ci = 0; ci < 64; ci++){
        __syncthreads();
        const float4* wg  = (const float4*)g_Weff[e][ci];
        float4*       ws4 = (float4*)w_s;
        #pragma unroll
        for (int t = 0; t < 6; t++){
            int u = tid + t*256;
            if (u < 81*16) ws4[u] = wg[u];
        }
        const float* sp = src + ((size_t)n*CCH + ids_s[ci]) * PLANE;
        #pragma unroll
        for (int t = 0; t < 3; t++){
            int u = tid + t*256;
            if (u < 640){
                int rr = u / 40, cc = u % 40;
                int r = y0 - 4 + rr, col = cc - 4;
                float v = 0.f;
                if (r >= 0 && r < HWD && col >= 0 && col < HWD) v = sp[r*HWD + col];
                in_s[u] = v;
            }
        }
        __syncthreads();

        const float* colbase = &in_s[lane];
        #pragma unroll 1
        for (int kx = 0; kx < 9; kx++){
            // 16-row input column at x = lane + kx - 4, broadcast-packed once
            unsigned long long vv[16];
            #pragma unroll
            for (int r = 0; r < 16; r++){
                float v = colbase[r*40 + kx];
                vv[r] = pack2(v, v);
            }
            bool kx_even = ((kx & 1) == 0);
            bool kx_mid  = (kx >= 1 && kx <= 7);
            const float* wcol = &w_s[kx*64 + og*8];
            #pragma unroll
            for (int ky = 0; ky < 9; ky++){
                bool do_tap;
                if (ky == 0 || ky == 8)      do_tap = kx_even;  // dilated ring rows
                else if ((ky & 1) == 1)      do_tap = kx_mid;   // odd rows: 7x7 interior
                else                          do_tap = true;     // even middle rows
                if (do_tap){
                    const ulonglong2* wp = (const ulonglong2*)(wcol + ky*9*64);
                    ulonglong2 wa = wp[0];   // oc pairs (0,1),(2,3)
                    ulonglong2 wb = wp[1];   // oc pairs (4,5),(6,7)
                    #pragma unroll
                    for (int r = 0; r < 8; r++){
                        fma2(acc[r],      wa.x, vv[r+ky]);
                        fma2(acc[8 + r],  wa.y, vv[r+ky]);
                        fma2(acc[16 + r], wb.x, vv[r+ky]);
                        fma2(acc[24 + r], wb.y, vv[r+ky]);
                    }
                }
            }
        }
    }

    // scatter-add: acc[p*8+r] holds oc (og*8+2p, og*8+2p+1) at pixel (y0+r, lane)
    size_t base = (size_t)n*CCH*PLANE;
    #pragma unroll
    for (int p = 0; p < 4; p++){
        int oc0 = ids_s[og*8 + 2*p];
        int oc1 = ids_s[og*8 + 2*p + 1];
        #pragma unroll
        for (int r = 0; r < 8; r++){
            float2 f = unpack2(acc[p*8 + r]);
            size_t po = (size_t)(y0 + r)*HWD + lane;
            dst[base + (size_t)oc0*PLANE + po] += f.x;
            dst[base + (size_t)oc1*PLANE + po] += f.y;
        }
    }
}

// ---------------- launch ----------------
extern "C" void kernel_launch(void* const* d_in, const int* in_sizes, int n_in,
                              void* d_out, int out_size){
    const float* x     = (const float*)d_in[0];
    const float* arch  = (const float*)d_in[1];
    const float* norms = (const float*)d_in[2];
    const int*   idx   = (const int*)  d_in[3];
    const float* w3c   = (const float*)d_in[4];
    const float* w5c   = (const float*)d_in[5];
    const float* w7c   = (const float*)d_in[6];
    const float* w1c   = (const float*)d_in[7];
    const float* s3dw  = (const float*)d_in[8];
    const float* s3pw  = (const float*)d_in[9];
    const float* s5dw  = (const float*)d_in[10];
    const float* s5pw  = (const float*)d_in[11];
    const float* d3c   = (const float*)d_in[12];
    const float* d5c   = (const float*)d_in[13];
    float* out = (float*)d_out;

    k_softmax<<<1, 32>>>(arch, norms);

    long long TOT = (long long)EDGES * PCH * 81 * PCH;
    int mb = (int)((TOT + 255) / 256);
    k_merge<<<mb, 256>>>(w3c, w5c, w7c, w1c, s3dw, s3pw, s5dw, s5pw, d3c, d5c);

    int e = 0;
    for (int node = 0; node < NODES; node++){
        for (int i = 0; i <= node; i++){
            if (i == 0) k_pool<true ><<<NB*CCH, 256>>>(x, out, e, i, node);
            else        k_pool<false><<<NB*CCH, 256>>>(x, out, e, i, node);
            k_conv<<<dim3(4, NB), 256>>>(x, out, idx, e, i, node);
            e++;
        }
    }
}

// round 5
// speedup vs baseline: 1.4612x; 1.0886x over previous
#include <cuda_runtime.h>
#include <math.h>

#define NODES 4
#define CCH 256
#define PCH 64
#define NB 64
#define HWD 32
#define PLANE (HWD*HWD)          // 1024
#define EDGES 10

// ---------------- device scratch (no allocations allowed) ----------------
__device__ float g_w[EDGES][12];
// merged 9x9 weights, layout [e][ci][tap(81)][o(64)]
__device__ float4 g_Weff[EDGES][PCH][81*16];
// intermediate node outputs (states[1..3]); final node writes d_out directly
__device__ float g_state[3][NB*CCH*PLANE];

__constant__ int c_edge_node[EDGES] = {0,1,1,2,2,2,3,3,3,3};
__constant__ int c_edge_i[EDGES]    = {0,0,1,0,1,2,0,1,2,3};

// ---------------- packed f32x2 helpers ----------------
__device__ __forceinline__ void fma2(unsigned long long &d, unsigned long long a, unsigned long long b){
    asm("fma.rn.f32x2 %0, %1, %2, %0;" : "+l"(d) : "l"(a), "l"(b));
}
__device__ __forceinline__ float2 unpack2(unsigned long long v){
    float2 f;
    asm("mov.b64 {%0, %1}, %2;" : "=f"(f.x), "=f"(f.y) : "l"(v));
    return f;
}

// ---------------- kernel 1: edge softmax weights ----------------
__global__ void k_softmax(const float* __restrict__ arch, const float* __restrict__ norms){
    int e = threadIdx.x;
    if (e >= EDGES) return;
    int node = c_edge_node[e], i = c_edge_i[e];
    float nrm = norms[node*(NODES+1)+i];
    nrm = fmaxf(nrm, 1e-5f);
    const float* a = arch + (size_t)(node*(NODES+1)+i)*12;
    float l[12], mx = -1e30f;
    #pragma unroll
    for (int k = 0; k < 12; k++){ l[k] = a[k] / nrm; mx = fmaxf(mx, l[k]); }
    float s = 0.f;
    #pragma unroll
    for (int k = 0; k < 12; k++){ l[k] = expf(l[k] - mx); s += l[k]; }
    float inv = 1.f / s;
    #pragma unroll
    for (int k = 0; k < 12; k++) g_w[e][k] = l[k] * inv;
}

// ---------------- kernel 2: merge all linear ops into one 9x9 dense conv ----------------
__global__ void k_merge(const float* __restrict__ w3c,  const float* __restrict__ w5c,
                        const float* __restrict__ w7c,  const float* __restrict__ w1c,
                        const float* __restrict__ s3dw, const float* __restrict__ s3pw,
                        const float* __restrict__ s5dw, const float* __restrict__ s5pw,
                        const float* __restrict__ d3c,  const float* __restrict__ d5c){
    long long t = (long long)blockIdx.x * blockDim.x + threadIdx.x;
    const long long TOT = (long long)EDGES * PCH * 81 * PCH;
    if (t >= TOT) return;
    int o  = (int)(t & 63);
    int kk = (int)((t >> 6) % 81);
    int i  = (int)(((t >> 6) / 81) % 64);
    int e  = (int)(t / (64LL*81*64));
    int ky = kk / 9, kx = kk % 9;
    int dy = ky - 4, dx = kx - 4;
    int ady = dy < 0 ? -dy : dy;
    int adx = dx < 0 ? -dx : dx;
    const float* w = g_w[e];
    long long oi = ((long long)e*64 + o)*64 + i;
    long long ei = (long long)e*64 + i;
    float val = 0.f;
    if (ady <= 3 && adx <= 3)
        val += w[3] * w7c[oi*49 + (dy+3)*7 + (dx+3)];
    if (ady <= 2 && adx <= 2){
        val += w[2] * w5c[oi*25 + (dy+2)*5 + (dx+2)];
        val += w[8] * s5pw[oi] * s5dw[ei*25 + (dy+2)*5 + (dx+2)];
    }
    if (ady <= 1 && adx <= 1){
        val += w[1] * w3c[oi*9 + (dy+1)*3 + (dx+1)];
        val += w[7] * s3pw[oi] * s3dw[ei*9 + (dy+1)*3 + (dx+1)];
    }
    if (dy == 0 && dx == 0){
        val += w[4] * w1c[oi];
        if (o == i) val += w[0];
    }
    if (((dy & 1) == 0) && ((dx & 1) == 0)){
        if (ady <= 2 && adx <= 2)
            val += w[9] * d3c[oi*9 + (dy/2+1)*3 + (dx/2+1)];
        val += w[10] * d5c[oi*25 + (dy/2+2)*5 + (dx/2+2)];
    }
    float* wf = (float*)g_Weff;
    wf[ (((long long)e*64 + i)*81 + kk)*64 + o ] = val;
}

// ---------------- kernel 3: max/avg 3x3 pooling accumulate (full 256 channels) ----------------
template<bool INIT>
__global__ void k_pool(const float* __restrict__ xin, float* __restrict__ dout,
                       int e, int src_sel, int dst_sel){
    const float* src = (src_sel == 0) ? xin : g_state[src_sel - 1];
    float* dst = (dst_sel == 3) ? dout : g_state[dst_sel];
    size_t base = (size_t)blockIdx.x * PLANE;
    __shared__ float tile[PLANE];
    for (int t = threadIdx.x; t < PLANE; t += 256) tile[t] = src[base + t];
    float w5v = g_w[e][5], w6v = g_w[e][6];
    __syncthreads();
    #pragma unroll
    for (int q = 0; q < 4; q++){
        int p = threadIdx.x + q*256;
        int y = p >> 5, x = p & 31;
        float m = -INFINITY, s = 0.f;
        #pragma unroll
        for (int dy = -1; dy <= 1; dy++){
            int yy = y + dy;
            if (yy < 0 || yy >= HWD) continue;
            #pragma unroll
            for (int dx = -1; dx <= 1; dx++){
                int xx = x + dx;
                if (xx < 0 || xx >= HWD) continue;
                float v = tile[yy*HWD + xx];
                m = fmaxf(m, v);
                s += v;
            }
        }
        float r = w5v*m + w6v*(s * (1.f/9.f));
        if (INIT) dst[base + p] = r;
        else      dst[base + p] += r;
    }
}

// ---------------- kernel 4: dense merged 9x9 conv, register-tiled 8oc x 8px ----------------
// block = 8x32 output tile of one image. warp = one oc-group of 8 channels.
// lane = output column x; thread accumulates 8 rows x 8 oc = 32 f32x2 regs.
// Input halo tile stored DUPLICATED in smem as float2{v,v}: inner loop does
// LDS.64 directly into the f32x2 operand pair -> zero packing MOVs (alu pipe).
// Rolling 8-entry window over input rows (compile-time rotation) keeps regs
// low enough for 2 CTAs/SM (launch_bounds(256,2)).
// kx is a runtime loop (small I$ footprint); ky fully unrolled.
// Zero taps of the merged 9x9 (16 of 81) skipped via uniform kx branches:
//   ky in {0,8}  -> active iff kx even
//   ky odd       -> active iff 1<=kx<=7
//   ky in {2,4,6}-> always active
__global__ __launch_bounds__(256, 2)
void k_conv(const float* __restrict__ xin, float* __restrict__ dout,
            const int* __restrict__ idx_all, int e, int src_sel, int dst_sel){
    const float* src = (src_sel == 0) ? xin : g_state[src_sel - 1];
    float* dst = (dst_sel == 3) ? dout : g_state[dst_sel];
    const int* ids = idx_all + e*64;

    int n   = blockIdx.y;
    int y0  = blockIdx.x * 8;
    int tid = threadIdx.x;
    int lane = tid & 31;   // output column x
    int og   = tid >> 5;   // oc group (warp id): oc = og*8 .. og*8+7

    __shared__ float  w_s[81*64];          // weights for current ci: [tap][o]
    __shared__ float2 in2_s[16*40];        // duplicated halo tile rows y0-4..y0+11, cols -4..35
    __shared__ int    ids_s[64];
    if (tid < 64) ids_s[tid] = ids[tid];

    unsigned long long acc[32];            // [ocpair(4)][row(8)]
    #pragma unroll
    for (int j = 0; j < 32; j++) acc[j] = 0ULL;

    for (int ci = 0; ci < 64; ci++){
        __syncthreads();
        const float4* wg  = (const float4*)g_Weff[e][ci];
        float4*       ws4 = (float4*)w_s;
        #pragma unroll
        for (int t = 0; t < 6; t++){
            int u = tid + t*256;
            if (u < 81*16) ws4[u] = wg[u];
        }
        const float* sp = src + ((size_t)n*CCH + ids_s[ci]) * PLANE;
        #pragma unroll
        for (int t = 0; t < 3; t++){
            int u = tid + t*256;
            if (u < 640){
                int rr = u / 40, cc = u % 40;
                int r = y0 - 4 + rr, col = cc - 4;
                float v = 0.f;
                if (r >= 0 && r < HWD && col >= 0 && col < HWD) v = sp[r*HWD + col];
                in2_s[u] = make_float2(v, v);
            }
        }
        __syncthreads();

        #pragma unroll 1
        for (int kx = 0; kx < 9; kx++){
            const unsigned long long* colp =
                (const unsigned long long*)&in2_s[lane + kx];   // row stride 40 float2
            bool kx_even = ((kx & 1) == 0);
            bool kx_mid  = (kx >= 1 && kx <= 7);
            const float* wcol = &w_s[kx*64 + og*8];

            // rolling window: win[(ky+r)&7] == input row ky+r
            unsigned long long win[8];
            #pragma unroll
            for (int j = 0; j < 8; j++) win[j] = colp[j*40];

            #pragma unroll
            for (int ky = 0; ky < 9; ky++){
                bool do_tap;
                if (ky == 0 || ky == 8)      do_tap = kx_even;  // dilated ring rows
                else if ((ky & 1) == 1)      do_tap = kx_mid;   // odd rows: 7x7 interior
                else                          do_tap = true;     // even middle rows
                if (do_tap){
                    const ulonglong2* wp = (const ulonglong2*)(wcol + ky*9*64);
                    ulonglong2 wa = wp[0];   // oc pairs (0,1),(2,3)
                    ulonglong2 wb = wp[1];   // oc pairs (4,5),(6,7)
                    #pragma unroll
                    for (int r = 0; r < 8; r++){
                        unsigned long long v = win[(ky + r) & 7];
                        fma2(acc[r],      wa.x, v);
                        fma2(acc[8 + r],  wa.y, v);
                        fma2(acc[16 + r], wb.x, v);
                        fma2(acc[24 + r], wb.y, v);
                    }
                }
                if (ky < 8) win[ky & 7] = colp[(ky + 8)*40];   // slide: bring in row ky+8
            }
        }
    }

    // scatter-add: acc[p*8+r] holds oc (og*8+2p, og*8+2p+1) at pixel (y0+r, lane)
    size_t base = (size_t)n*CCH*PLANE;
    #pragma unroll
    for (int p = 0; p < 4; p++){
        int oc0 = ids_s[og*8 + 2*p];
        int oc1 = ids_s[og*8 + 2*p + 1];
        #pragma unroll
        for (int r = 0; r < 8; r++){
            float2 f = unpack2(acc[p*8 + r]);
            size_t po = (size_t)(y0 + r)*HWD + lane;
            dst[base + (size_t)oc0*PLANE + po] += f.x;
            dst[base + (size_t)oc1*PLANE + po] += f.y;
        }
    }
}

// ---------------- launch ----------------
extern "C" void kernel_launch(void* const* d_in, const int* in_sizes, int n_in,
                              void* d_out, int out_size){
    const float* x     = (const float*)d_in[0];
    const float* arch  = (const float*)d_in[1];
    const float* norms = (const float*)d_in[2];
    const int*   idx   = (const int*)  d_in[3];
    const float* w3c   = (const float*)d_in[4];
    const float* w5c   = (const float*)d_in[5];
    const float* w7c   = (const float*)d_in[6];
    const float* w1c   = (const float*)d_in[7];
    const float* s3dw  = (const float*)d_in[8];
    const float* s3pw  = (const float*)d_in[9];
    const float* s5dw  = (const float*)d_in[10];
    const float* s5pw  = (const float*)d_in[11];
    const float* d3c   = (const float*)d_in[12];
    const float* d5c   = (const float*)d_in[13];
    float* out = (float*)d_out;

    k_softmax<<<1, 32>>>(arch, norms);

    long long TOT = (long long)EDGES * PCH * 81 * PCH;
    int mb = (int)((TOT + 255) / 256);
    k_merge<<<mb, 256>>>(w3c, w5c, w7c, w1c, s3dw, s3pw, s5dw, s5pw, d3c, d5c);

    int e = 0;
    for (int node = 0; node < NODES; node++){
        for (int i = 0; i <= node; i++){
            if (i == 0) k_pool<true ><<<NB*CCH, 256>>>(x, out, e, i, node);
            else        k_pool<false><<<NB*CCH, 256>>>(x, out, e, i, node);
            k_conv<<<dim3(4, NB), 256>>>(x, out, idx, e, i, node);
            e++;
        }
    }
}

// round 7
// speedup vs baseline: 4.2107x; 2.8817x over previous
#include <cuda_runtime.h>
#include <math.h>
#include <stdint.h>

#define NODES 4
#define CCH 256
#define PCH 64
#define NB 64
#define HWD 32
#define PLANE 1024
#define EDGES 10

// ---------------- device scratch ----------------
__device__ float g_w[EDGES][12];
__device__ float g_state[3][(size_t)NB*CCH*PLANE];
// MMA B operand: [e][ci][oc][k(72)] tf32 bits (zeros at pad taps 65..71)
__device__ float g_Bk[(size_t)EDGES*64*64*72];

__constant__ int c_edge_node[EDGES] = {0,1,1,2,2,2,3,3,3,3};
__constant__ int c_edge_i[EDGES]    = {0,0,1,0,1,2,0,1,2,3};

// active taps of merged 9x9 (65 of 81): interior 7x7  OR  even-even (dilated)
__constant__ signed char c_tdy[65] = {
    -4,-4,-4,-4,-4,
    -3,-3,-3,-3,-3,-3,-3,
    -2,-2,-2,-2,-2,-2,-2,-2,-2,
    -1,-1,-1,-1,-1,-1,-1,
     0, 0, 0, 0, 0, 0, 0, 0, 0,
     1, 1, 1, 1, 1, 1, 1,
     2, 2, 2, 2, 2, 2, 2, 2, 2,
     3, 3, 3, 3, 3, 3, 3,
     4, 4, 4, 4, 4};
__constant__ signed char c_tdx[65] = {
    -4,-2, 0, 2, 4,
    -3,-2,-1, 0, 1, 2, 3,
    -4,-3,-2,-1, 0, 1, 2, 3, 4,
    -3,-2,-1, 0, 1, 2, 3,
    -4,-3,-2,-1, 0, 1, 2, 3, 4,
    -3,-2,-1, 0, 1, 2, 3,
    -4,-3,-2,-1, 0, 1, 2, 3, 4,
    -3,-2,-1, 0, 1, 2, 3,
    -4,-2, 0, 2, 4};

__device__ __forceinline__ uint32_t cvt_tf32(float v){
    uint32_t r; asm("cvt.rna.tf32.f32 %0, %1;" : "=r"(r) : "f"(v)); return r;
}
__device__ __forceinline__ void mma_tf32(float* d, const uint32_t* a, uint32_t b0, uint32_t b1){
    asm volatile("mma.sync.aligned.m16n8k8.row.col.f32.tf32.tf32.f32 "
        "{%0,%1,%2,%3}, {%4,%5,%6,%7}, {%8,%9}, {%0,%1,%2,%3};"
        : "+f"(d[0]), "+f"(d[1]), "+f"(d[2]), "+f"(d[3])
        : "r"(a[0]), "r"(a[1]), "r"(a[2]), "r"(a[3]), "r"(b0), "r"(b1));
}

// ---------------- kernel 1: edge softmax ----------------
__global__ void k_softmax(const float* __restrict__ arch, const float* __restrict__ norms){
    int e = threadIdx.x;
    if (e >= EDGES) return;
    int node = c_edge_node[e], i = c_edge_i[e];
    float nrm = fmaxf(norms[node*(NODES+1)+i], 1e-5f);
    const float* a = arch + (size_t)(node*(NODES+1)+i)*12;
    float l[12], mx = -1e30f;
    #pragma unroll
    for (int k = 0; k < 12; k++){ l[k] = a[k] / nrm; mx = fmaxf(mx, l[k]); }
    float s = 0.f;
    #pragma unroll
    for (int k = 0; k < 12; k++){ l[k] = expf(l[k] - mx); s += l[k]; }
    float inv = 1.f / s;
    #pragma unroll
    for (int k = 0; k < 12; k++) g_w[e][k] = l[k] * inv;
}

// ---------------- kernel 2: merge ops into tf32 B tiles [e][ci][oc][72] ----------------
__global__ void k_mergeB(const float* __restrict__ w3c,  const float* __restrict__ w5c,
                         const float* __restrict__ w7c,  const float* __restrict__ w1c,
                         const float* __restrict__ s3dw, const float* __restrict__ s3pw,
                         const float* __restrict__ s5dw, const float* __restrict__ s5pw,
                         const float* __restrict__ d3c,  const float* __restrict__ d5c){
    long long t = (long long)blockIdx.x * blockDim.x + threadIdx.x;
    const long long TOT = (long long)EDGES * 64 * 64 * 72;
    if (t >= TOT) return;
    int k   = (int)(t % 72);
    long long r1 = t / 72;
    int o   = (int)(r1 & 63);
    long long r2 = r1 >> 6;
    int i   = (int)(r2 & 63);
    int e   = (int)(r2 >> 6);
    float val = 0.f;
    if (k < 65){
        int dy = c_tdy[k], dx = c_tdx[k];
        int ady = dy < 0 ? -dy : dy;
        int adx = dx < 0 ? -dx : dx;
        const float* w = g_w[e];
        long long oi = ((long long)e*64 + o)*64 + i;
        long long ei = (long long)e*64 + i;
        if (ady <= 3 && adx <= 3)
            val += w[3] * w7c[oi*49 + (dy+3)*7 + (dx+3)];
        if (ady <= 2 && adx <= 2){
            val += w[2] * w5c[oi*25 + (dy+2)*5 + (dx+2)];
            val += w[8] * s5pw[oi] * s5dw[ei*25 + (dy+2)*5 + (dx+2)];
        }
        if (ady <= 1 && adx <= 1){
            val += w[1] * w3c[oi*9 + (dy+1)*3 + (dx+1)];
            val += w[7] * s3pw[oi] * s3dw[ei*9 + (dy+1)*3 + (dx+1)];
        }
        if (dy == 0 && dx == 0){
            val += w[4] * w1c[oi];
            if (o == i) val += w[0];
        }
        if (((dy & 1) == 0) && ((dx & 1) == 0)){
            if (ady <= 2 && adx <= 2)
                val += w[9] * d3c[oi*9 + (dy/2+1)*3 + (dx/2+1)];
            val += w[10] * d5c[oi*25 + (dy/2+2)*5 + (dx/2+2)];
        }
    }
    g_Bk[t] = __uint_as_float(cvt_tf32(val));
}

// ---------------- kernel 3: max/avg pooling accumulate ----------------
template<bool INIT>
__global__ void k_pool(const float* __restrict__ xin, float* __restrict__ dout,
                       int e, int src_sel, int dst_sel){
    const float* src = (src_sel == 0) ? xin : g_state[src_sel - 1];
    float* dst = (dst_sel == 3) ? dout : g_state[dst_sel];
    size_t base = (size_t)blockIdx.x * PLANE;
    __shared__ float tile[PLANE];
    for (int t = threadIdx.x; t < PLANE; t += 256) tile[t] = src[base + t];
    float w5v = g_w[e][5], w6v = g_w[e][6];
    __syncthreads();
    #pragma unroll
    for (int q = 0; q < 4; q++){
        int p = threadIdx.x + q*256;
        int y = p >> 5, x = p & 31;
        float m = -INFINITY, s = 0.f;
        #pragma unroll
        for (int dy = -1; dy <= 1; dy++){
            int yy = y + dy;
            if (yy < 0 || yy >= HWD) continue;
            #pragma unroll
            for (int dx = -1; dx <= 1; dx++){
                int xx = x + dx;
                if (xx < 0 || xx >= HWD) continue;
                float v = tile[yy*HWD + xx];
                m = fmaxf(m, v);
                s += v;
            }
        }
        float r = w5v*m + w6v*(s * (1.f/9.f));
        if (INIT) dst[base + p] = r;
        else      dst[base + p] += r;
    }
}

// ---------------- kernel 4: tf32 mma.sync implicit-GEMM conv ----------------
// CTA = 8 image rows (256 px) x 64 oc. Warp = one image row (32 px = two m16
// fragments) x 64 oc (8 n-frags) -> 64 fp32 accumulator regs.
// Loop over ci: stage gathered plane (16x40 halo tile) + B tile (oc-major,
// stride 76 words -> conflict-free B fragment loads). A fragments read
// directly from the plane tile via a per-(kc,lane) tap-offset table (no
// im2col materialization); a1/a3 = a0/a2 address + 8.
__global__ __launch_bounds__(256)
void k_mma(const float* __restrict__ xin, float* __restrict__ dout,
           const int* __restrict__ idx_all, int e, int src_sel, int dst_sel){
    const float* src = (src_sel == 0) ? xin : g_state[src_sel - 1];
    float* dst = (dst_sel == 3) ? dout : g_state[dst_sel];

    __shared__ float pl[16*40];      // rows R0-4..R0+11, cols -4..35 (zero halo)
    __shared__ float Bs[64*76];      // [oc][k] stride 76
    __shared__ int   ids_s[64];
    __shared__ int   toff[72];       // tap -> dy*40+dx (0 for pad taps)

    int n   = blockIdx.y;
    int R0  = blockIdx.x * 8;
    int tid = threadIdx.x;
    int lane = tid & 31;
    int w    = tid >> 5;             // warp = image row R0 + w

    if (tid < 64) ids_s[tid] = idx_all[e*64 + tid];
    if (tid < 72) toff[tid] = (tid < 65) ? ((int)c_tdy[tid]*40 + (int)c_tdx[tid]) : 0;

    float acc[2][8][4];
    #pragma unroll
    for (int f = 0; f < 2; f++)
        #pragma unroll
        for (int nf = 0; nf < 8; nf++)
            #pragma unroll
            for (int q = 0; q < 4; q++) acc[f][nf][q] = 0.f;

    int pbase = (w + 4)*40 + 4 + (lane >> 2);
    __syncthreads();

    for (int ci = 0; ci < 64; ci++){
        if (ci) __syncthreads();
        // stage gathered input plane rows with zero halo
        const float* sp = src + ((size_t)n*CCH + ids_s[ci]) * PLANE;
        for (int u = tid; u < 640; u += 256){
            int r = u / 40, c = u - r*40;
            int gy = R0 - 4 + r, gx = c - 4;
            float v = 0.f;
            if (gy >= 0 && gy < HWD && gx >= 0 && gx < HWD) v = sp[gy*HWD + gx];
            pl[u] = v;
        }
        // stage B tile: [oc][72] float4s -> smem stride 76
        const float4* bsrc = (const float4*)(g_Bk + (size_t)(e*64 + ci)*64*72);
        for (int u = tid; u < 1152; u += 256){
            int oc = u / 18, kq = u - oc*18;
            *(float4*)&Bs[oc*76 + kq*4] = bsrc[u];
        }
        __syncthreads();

        #pragma unroll
        for (int kc = 0; kc < 9; kc++){
            int o0 = toff[kc*8 + (lane & 3)];
            int o1 = toff[kc*8 + 4 + (lane & 3)];
            uint32_t a[2][4];
            #pragma unroll
            for (int f = 0; f < 2; f++){
                int pb = pbase + f*16;
                a[f][0] = cvt_tf32(pl[pb + o0]);
                a[f][1] = cvt_tf32(pl[pb + 8 + o0]);
                a[f][2] = cvt_tf32(pl[pb + o1]);
                a[f][3] = cvt_tf32(pl[pb + 8 + o1]);
            }
            const uint32_t* bu = (const uint32_t*)Bs;
            #pragma unroll
            for (int nf = 0; nf < 8; nf++){
                int bi = (nf*8 + (lane >> 2))*76 + kc*8 + (lane & 3);
                uint32_t b0 = bu[bi];
                uint32_t b1 = bu[bi + 4];
                mma_tf32(acc[0][nf], a[0], b0, b1);
                mma_tf32(acc[1][nf], a[1], b0, b1);
            }
        }
    }

    // epilogue: scatter-add. D frag (m16n8): rows lane>>2 (+8), cols 2*(lane&3)+{0,1}
    int y = R0 + w;
    size_t nb = (size_t)n*CCH*PLANE + (size_t)y*HWD;
    #pragma unroll
    for (int f = 0; f < 2; f++){
        int x0 = f*16 + (lane >> 2);
        #pragma unroll
        for (int nf = 0; nf < 8; nf++){
            int oc = nf*8 + 2*(lane & 3);
            size_t p0 = nb + (size_t)ids_s[oc]*PLANE;
            size_t p1 = nb + (size_t)ids_s[oc+1]*PLANE;
            dst[p0 + x0]     += acc[f][nf][0];
            dst[p1 + x0]     += acc[f][nf][1];
            dst[p0 + x0 + 8] += acc[f][nf][2];
            dst[p1 + x0 + 8] += acc[f][nf][3];
        }
    }
}

// ---------------- launch ----------------
extern "C" void kernel_launch(void* const* d_in, const int* in_sizes, int n_in,
                              void* d_out, int out_size){
    const float* x     = (const float*)d_in[0];
    const float* arch  = (const float*)d_in[1];
    const float* norms = (const float*)d_in[2];
    const int*   idx   = (const int*)  d_in[3];
    const float* w3c   = (const float*)d_in[4];
    const float* w5c   = (const float*)d_in[5];
    const float* w7c   = (const float*)d_in[6];
    const float* w1c   = (const float*)d_in[7];
    const float* s3dw  = (const float*)d_in[8];
    const float* s3pw  = (const float*)d_in[9];
    const float* s5dw  = (const float*)d_in[10];
    const float* s5pw  = (const float*)d_in[11];
    const float* d3c   = (const float*)d_in[12];
    const float* d5c   = (const float*)d_in[13];
    float* out = (float*)d_out;

    k_softmax<<<1, 32>>>(arch, norms);

    long long TOT = (long long)EDGES * 64 * 64 * 72;
    int mb = (int)((TOT + 255) / 256);
    k_mergeB<<<mb, 256>>>(w3c, w5c, w7c, w1c, s3dw, s3pw, s5dw, s5pw, d3c, d5c);

    int e = 0;
    for (int node = 0; node < NODES; node++){
        for (int i = 0; i <= node; i++){
            if (i == 0) k_pool<true ><<<NB*CCH, 256>>>(x, out, e, i, node);
            else        k_pool<false><<<NB*CCH, 256>>>(x, out, e, i, node);
            k_mma<<<dim3(4, NB), 256>>>(x, out, idx, e, i, node);
            e++;
        }
    }
}

// round 8
// speedup vs baseline: 4.8613x; 1.1545x over previous
#include <cuda_runtime.h>
#include <math.h>
#include <stdint.h>

#define NODES 4
#define CCH 256
#define PCH 64
#define NB 64
#define HWD 32
#define PLANE 1024
#define EDGES 10

// ---------------- device scratch ----------------
__device__ float g_w[EDGES][12];
__device__ float g_state[3][(size_t)NB*CCH*PLANE];
// MMA B operand: [e][ci][oc][k(72)], k-pair interleaved within 8-groups:
// slot kc*8 + j*2 + h  holds orig k = kc*8 + j + 4h   (zeros at pad taps)
__device__ float g_Bk[(size_t)EDGES*64*64*72];

__constant__ int c_edge_node[EDGES] = {0,1,1,2,2,2,3,3,3,3};
__constant__ int c_edge_i[EDGES]    = {0,0,1,0,1,2,0,1,2,3};

// active taps of merged 9x9 (65 of 81): interior 7x7  OR  even-even (dilated)
__constant__ signed char c_tdy[65] = {
    -4,-4,-4,-4,-4,
    -3,-3,-3,-3,-3,-3,-3,
    -2,-2,-2,-2,-2,-2,-2,-2,-2,
    -1,-1,-1,-1,-1,-1,-1,
     0, 0, 0, 0, 0, 0, 0, 0, 0,
     1, 1, 1, 1, 1, 1, 1,
     2, 2, 2, 2, 2, 2, 2, 2, 2,
     3, 3, 3, 3, 3, 3, 3,
     4, 4, 4, 4, 4};
__constant__ signed char c_tdx[65] = {
    -4,-2, 0, 2, 4,
    -3,-2,-1, 0, 1, 2, 3,
    -4,-3,-2,-1, 0, 1, 2, 3, 4,
    -3,-2,-1, 0, 1, 2, 3,
    -4,-3,-2,-1, 0, 1, 2, 3, 4,
    -3,-2,-1, 0, 1, 2, 3,
    -4,-3,-2,-1, 0, 1, 2, 3, 4,
    -3,-2,-1, 0, 1, 2, 3,
    -4,-2, 0, 2, 4};

__device__ __forceinline__ uint32_t cvt_tf32(float v){
    uint32_t r; asm("cvt.rna.tf32.f32 %0, %1;" : "=r"(r) : "f"(v)); return r;
}
__device__ __forceinline__ void mma_tf32(float* d, const uint32_t* a, uint32_t b0, uint32_t b1){
    asm volatile("mma.sync.aligned.m16n8k8.row.col.f32.tf32.tf32.f32 "
        "{%0,%1,%2,%3}, {%4,%5,%6,%7}, {%8,%9}, {%0,%1,%2,%3};"
        : "+f"(d[0]), "+f"(d[1]), "+f"(d[2]), "+f"(d[3])
        : "r"(a[0]), "r"(a[1]), "r"(a[2]), "r"(a[3]), "r"(b0), "r"(b1));
}
__device__ __forceinline__ uint32_t smem_u32(const void* p){
    uint32_t a;
    asm("{ .reg .u64 t; cvta.to.shared.u64 t, %1; cvt.u32.u64 %0, t; }" : "=r"(a) : "l"(p));
    return a;
}
__device__ __forceinline__ void cpa4(uint32_t dst, const void* src, int srcsz){
    asm volatile("cp.async.ca.shared.global [%0], [%1], 4, %2;"
                 :: "r"(dst), "l"(src), "r"(srcsz) : "memory");
}
__device__ __forceinline__ void cpa16(uint32_t dst, const void* src){
    asm volatile("cp.async.cg.shared.global [%0], [%1], 16;"
                 :: "r"(dst), "l"(src) : "memory");
}
#define CP_COMMIT() asm volatile("cp.async.commit_group;" ::: "memory")
#define CP_WAIT0()  asm volatile("cp.async.wait_group 0;" ::: "memory")

// ---------------- kernel 1: edge softmax ----------------
__global__ void k_softmax(const float* __restrict__ arch, const float* __restrict__ norms){
    int e = threadIdx.x;
    if (e >= EDGES) return;
    int node = c_edge_node[e], i = c_edge_i[e];
    float nrm = fmaxf(norms[node*(NODES+1)+i], 1e-5f);
    const float* a = arch + (size_t)(node*(NODES+1)+i)*12;
    float l[12], mx = -1e30f;
    #pragma unroll
    for (int k = 0; k < 12; k++){ l[k] = a[k] / nrm; mx = fmaxf(mx, l[k]); }
    float s = 0.f;
    #pragma unroll
    for (int k = 0; k < 12; k++){ l[k] = expf(l[k] - mx); s += l[k]; }
    float inv = 1.f / s;
    #pragma unroll
    for (int k = 0; k < 12; k++) g_w[e][k] = l[k] * inv;
}

// ---------------- kernel 2: merge ops into tf32 B tiles ----------------
__global__ void k_mergeB(const float* __restrict__ w3c,  const float* __restrict__ w5c,
                         const float* __restrict__ w7c,  const float* __restrict__ w1c,
                         const float* __restrict__ s3dw, const float* __restrict__ s3pw,
                         const float* __restrict__ s5dw, const float* __restrict__ s5pw,
                         const float* __restrict__ d3c,  const float* __restrict__ d5c){
    long long t = (long long)blockIdx.x * blockDim.x + threadIdx.x;
    const long long TOT = (long long)EDGES * 64 * 64 * 72;
    if (t >= TOT) return;
    int k   = (int)(t % 72);           // ORIGINAL k index
    long long r1 = t / 72;
    int o   = (int)(r1 & 63);
    long long r2 = r1 >> 6;
    int i   = (int)(r2 & 63);
    int e   = (int)(r2 >> 6);
    float val = 0.f;
    if (k < 65){
        int dy = c_tdy[k], dx = c_tdx[k];
        int ady = dy < 0 ? -dy : dy;
        int adx = dx < 0 ? -dx : dx;
        const float* w = g_w[e];
        long long oi = ((long long)e*64 + o)*64 + i;
        long long ei = (long long)e*64 + i;
        if (ady <= 3 && adx <= 3)
            val += w[3] * w7c[oi*49 + (dy+3)*7 + (dx+3)];
        if (ady <= 2 && adx <= 2){
            val += w[2] * w5c[oi*25 + (dy+2)*5 + (dx+2)];
            val += w[8] * s5pw[oi] * s5dw[ei*25 + (dy+2)*5 + (dx+2)];
        }
        if (ady <= 1 && adx <= 1){
            val += w[1] * w3c[oi*9 + (dy+1)*3 + (dx+1)];
            val += w[7] * s3pw[oi] * s3dw[ei*9 + (dy+1)*3 + (dx+1)];
        }
        if (dy == 0 && dx == 0){
            val += w[4] * w1c[oi];
            if (o == i) val += w[0];
        }
        if (((dy & 1) == 0) && ((dx & 1) == 0)){
            if (ady <= 2 && adx <= 2)
                val += w[9] * d3c[oi*9 + (dy/2+1)*3 + (dx/2+1)];
            val += w[10] * d5c[oi*25 + (dy/2+2)*5 + (dx/2+2)];
        }
    }
    // pair-interleaved slot: within each group of 8, (j,h) -> j*2+h
    int kc = k >> 3, r = k & 7;
    int slot = kc*8 + (r & 3)*2 + (r >> 2);
    g_Bk[(r1*72) + slot] = __uint_as_float(cvt_tf32(val));
}

// ---------------- kernel 3: max/avg pooling accumulate ----------------
template<bool INIT>
__global__ void k_pool(const float* __restrict__ xin, float* __restrict__ dout,
                       int e, int src_sel, int dst_sel){
    const float* src = (src_sel == 0) ? xin : g_state[src_sel - 1];
    float* dst = (dst_sel == 3) ? dout : g_state[dst_sel];
    size_t base = (size_t)blockIdx.x * PLANE;
    __shared__ float tile[PLANE];
    for (int t = threadIdx.x; t < PLANE; t += 256) tile[t] = src[base + t];
    float w5v = g_w[e][5], w6v = g_w[e][6];
    __syncthreads();
    #pragma unroll
    for (int q = 0; q < 4; q++){
        int p = threadIdx.x + q*256;
        int y = p >> 5, x = p & 31;
        float m = -INFINITY, s = 0.f;
        #pragma unroll
        for (int dy = -1; dy <= 1; dy++){
            int yy = y + dy;
            if (yy < 0 || yy >= HWD) continue;
            #pragma unroll
            for (int dx = -1; dx <= 1; dx++){
                int xx = x + dx;
                if (xx < 0 || xx >= HWD) continue;
                float v = tile[yy*HWD + xx];
                m = fmaxf(m, v);
                s += v;
            }
        }
        float r = w5v*m + w6v*(s * (1.f/9.f));
        if (INIT) dst[base + p] = r;
        else      dst[base + p] += r;
    }
}

// ---------------- kernel 4: tf32 mma.sync implicit-GEMM, cp.async pipelined ----------------
// CTA = 8 image rows x 64 oc. Warp = one row (two m16 frags) x 64 oc.
// Double-buffered plane + B tiles; next-ci staged via cp.async issued BEFORE
// the MMA loop, waited after -> global latency hidden; ONE syncthreads per ci.
__global__ __launch_bounds__(256)
void k_mma(const float* __restrict__ xin, float* __restrict__ dout,
           const int* __restrict__ idx_all, int e, int src_sel, int dst_sel){
    const float* src = (src_sel == 0) ? xin : g_state[src_sel - 1];
    float* dst = (dst_sel == 3) ? dout : g_state[dst_sel];

    __shared__ float pl[2][640];       // rows R0-4..R0+11, cols -4..35 (zero halo)
    __shared__ float Bs[2][64*76];     // [oc][k-slot] stride 76
    __shared__ int   ids_s[64];
    __shared__ int   toff[72];

    int n   = blockIdx.y;
    int R0  = blockIdx.x * 8;
    int tid = threadIdx.x;
    int lane = tid & 31;
    int w    = tid >> 5;

    if (tid < 64) ids_s[tid] = idx_all[e*64 + tid];
    if (tid < 72) toff[tid] = (tid < 65) ? ((int)c_tdy[tid]*40 + (int)c_tdx[tid]) : 0;

    // ci-invariant staging descriptors
    int p_off[3], p_sz[3];
    uint32_t p_d[3];
    #pragma unroll
    for (int t = 0; t < 3; t++){
        int u = tid + t*256;
        bool have = (u < 640);
        int r = u / 40, c = u - r*40;
        int gy = R0 - 4 + r, gx = c - 4;
        bool ok = have && gy >= 0 && gy < HWD && gx >= 0 && gx < HWD;
        p_off[t] = ok ? (gy*HWD + gx) : 0;
        p_sz[t]  = ok ? 4 : 0;
        p_d[t]   = have ? (u*4) : 0xFFFFFFFFu;   // sentinel for inactive
    }
    uint32_t b_d[5]; int b_u[5];
    #pragma unroll
    for (int t = 0; t < 5; t++){
        int u = tid + t*256;
        bool have = (u < 1152);
        int oc = u / 18, kq = u - oc*18;
        b_d[t] = (oc*76 + kq*4)*4;
        b_u[t] = have ? u : -1;
    }
    uint32_t plb[2] = { smem_u32(&pl[0][0]), smem_u32(&pl[1][0]) };
    uint32_t bsb[2] = { smem_u32(&Bs[0][0]), smem_u32(&Bs[1][0]) };
    const char* bkbase = (const char*)(g_Bk + (size_t)e*64*64*72);
    size_t nbase = (size_t)n*CCH*PLANE;
    __syncthreads();   // ids_s ready

    // prologue: stage ci=0 into buffer 0
    {
        const float* sp = src + nbase + (size_t)ids_s[0]*PLANE;
        #pragma unroll
        for (int t = 0; t < 3; t++)
            if (p_d[t] != 0xFFFFFFFFu) cpa4(plb[0] + p_d[t], sp + p_off[t], p_sz[t]);
        const char* bp = bkbase;   // ci = 0
        #pragma unroll
        for (int t = 0; t < 5; t++)
            if (b_u[t] >= 0) cpa16(bsb[0] + b_d[t], bp + (size_t)b_u[t]*16);
        CP_COMMIT();
        CP_WAIT0();
    }
    __syncthreads();

    float acc[2][8][4];
    #pragma unroll
    for (int f = 0; f < 2; f++)
        #pragma unroll
        for (int nf = 0; nf < 8; nf++)
            #pragma unroll
            for (int q = 0; q < 4; q++) acc[f][nf][q] = 0.f;

    int pbase = (w + 4)*40 + 4 + (lane >> 2);

    for (int ci = 0; ci < 64; ci++){
        int cur = ci & 1;
        // prefetch ci+1 into other buffer (reads of that buffer finished at
        // the barrier closing iteration ci-1)
        if (ci < 63){
            const float* sp = src + nbase + (size_t)ids_s[ci+1]*PLANE;
            #pragma unroll
            for (int t = 0; t < 3; t++)
                if (p_d[t] != 0xFFFFFFFFu) cpa4(plb[cur^1] + p_d[t], sp + p_off[t], p_sz[t]);
            const char* bp = bkbase + (size_t)(ci+1)*4608*4;
            #pragma unroll
            for (int t = 0; t < 5; t++)
                if (b_u[t] >= 0) cpa16(bsb[cur^1] + b_d[t], bp + (size_t)b_u[t]*16);
            CP_COMMIT();
        }

        const float* plc = pl[cur];
        const float* bsc = Bs[cur];
        #pragma unroll
        for (int kc = 0; kc < 9; kc++){
            int o0 = toff[kc*8 + (lane & 3)];
            int o1 = toff[kc*8 + 4 + (lane & 3)];
            uint32_t a[2][4];
            #pragma unroll
            for (int f = 0; f < 2; f++){
                int pb = pbase + f*16;
                a[f][0] = cvt_tf32(plc[pb + o0]);
                a[f][1] = cvt_tf32(plc[pb + 8 + o0]);
                a[f][2] = cvt_tf32(plc[pb + o1]);
                a[f][3] = cvt_tf32(plc[pb + 8 + o1]);
            }
            #pragma unroll
            for (int nf = 0; nf < 8; nf++){
                int bi = (nf*8 + (lane >> 2))*76 + kc*8 + (lane & 3)*2;
                float2 bb = *(const float2*)(bsc + bi);
                uint32_t b0 = __float_as_uint(bb.x);
                uint32_t b1 = __float_as_uint(bb.y);
                mma_tf32(acc[0][nf], a[0], b0, b1);
                mma_tf32(acc[1][nf], a[1], b0, b1);
            }
        }
        CP_WAIT0();
        __syncthreads();
    }

    // epilogue: scatter-add. D frag (m16n8): rows lane>>2 (+8), cols 2*(lane&3)+{0,1}
    int y = R0 + w;
    size_t nb = nbase + (size_t)y*HWD;
    #pragma unroll
    for (int f = 0; f < 2; f++){
        int x0 = f*16 + (lane >> 2);
        #pragma unroll
        for (int nf = 0; nf < 8; nf++){
            int oc = nf*8 + 2*(lane & 3);
            size_t p0 = nb + (size_t)ids_s[oc]*PLANE;
            size_t p1 = nb + (size_t)ids_s[oc+1]*PLANE;
            dst[p0 + x0]     += acc[f][nf][0];
            dst[p1 + x0]     += acc[f][nf][1];
            dst[p0 + x0 + 8] += acc[f][nf][2];
            dst[p1 + x0 + 8] += acc[f][nf][3];
        }
    }
}

// ---------------- launch ----------------
extern "C" void kernel_launch(void* const* d_in, const int* in_sizes, int n_in,
                              void* d_out, int out_size){
    const float* x     = (const float*)d_in[0];
    const float* arch  = (const float*)d_in[1];
    const float* norms = (const float*)d_in[2];
    const int*   idx   = (const int*)  d_in[3];
    const float* w3c   = (const float*)d_in[4];
    const float* w5c   = (const float*)d_in[5];
    const float* w7c   = (const float*)d_in[6];
    const float* w1c   = (const float*)d_in[7];
    const float* s3dw  = (const float*)d_in[8];
    const float* s3pw  = (const float*)d_in[9];
    const float* s5dw  = (const float*)d_in[10];
    const float* s5pw  = (const float*)d_in[11];
    const float* d3c   = (const float*)d_in[12];
    const float* d5c   = (const float*)d_in[13];
    float* out = (float*)d_out;

    k_softmax<<<1, 32>>>(arch, norms);

    long long TOT = (long long)EDGES * 64 * 64 * 72;
    int mb = (int)((TOT + 255) / 256);
    k_mergeB<<<mb, 256>>>(w3c, w5c, w7c, w1c, s3dw, s3pw, s5dw, s5pw, d3c, d5c);

    int e = 0;
    for (int node = 0; node < NODES; node++){
        for (int i = 0; i <= node; i++){
            if (i == 0) k_pool<true ><<<NB*CCH, 256>>>(x, out, e, i, node);
            else        k_pool<false><<<NB*CCH, 256>>>(x, out, e, i, node);
            k_mma<<<dim3(4, NB), 256>>>(x, out, idx, e, i, node);
            e++;
        }
    }
}

// round 9
// speedup vs baseline: 5.4578x; 1.1227x over previous
#include <cuda_runtime.h>
#include <math.h>
#include <stdint.h>

#define NODES 4
#define CCH 256
#define PCH 64
#define NB 64
#define HWD 32
#define PLANE 1024
#define EDGES 10

// ---------------- device scratch ----------------
__device__ float g_w[EDGES][12];
__device__ float g_state[3][(size_t)NB*CCH*PLANE];
// MMA B operand: [e][ci][oc][72 slots] tf32, k-pair interleaved per 8-group:
// smem/global pos kc*8 + j*2 + h  holds slot kc*8 + j + 4h  (j=0..3, h=0..1)
__device__ float g_Bk[(size_t)EDGES*64*64*72];

__constant__ int c_edge_node[EDGES] = {0,1,1,2,2,2,3,3,3,3};
__constant__ int c_edge_i[EDGES]    = {0,0,1,0,1,2,0,1,2,3};

// Column-grouped tap table, slot s = kc*8 + idx. dy=99 marks pad (weight 0).
// Bank-conflict-free: within each A-fragment LDS, the 4 taps' (40dy+dx) mod 32
// differ by 8 -> with lane>>2 offset, all 32 banks distinct.
__constant__ signed char c_sdy[72] = {
    -3,-2,-1, 0, 1, 2, 3,99,   // kc0 dx=-3
    -3,-2,-1, 0, 1, 2, 3,99,   // kc1 dx=-1
    -3,-2,-1, 0, 1, 2, 3,99,   // kc2 dx=+1
    -3,-2,-1, 0, 1, 2, 3,99,   // kc3 dx=+3
    -4,-3,-2,-1, 0, 1, 2, 3,   // kc4 dx=-2
    -4,-3,-2,-1, 0, 1, 2, 3,   // kc5 dx= 0
    -4,-3,-2,-1, 0, 1, 2, 3,   // kc6 dx=+2
    -4,-2,-4,-2, 0, 2, 0, 2,   // kc7 dx= -4,-4,+4,+4,-4,-4,+4,+4
     4, 4, 4, 4, 4,99,99,99};  // kc8 dy=4 row
__constant__ signed char c_sdx[72] = {
    -3,-3,-3,-3,-3,-3,-3, 0,
    -1,-1,-1,-1,-1,-1,-1, 0,
     1, 1, 1, 1, 1, 1, 1, 0,
     3, 3, 3, 3, 3, 3, 3, 0,
    -2,-2,-2,-2,-2,-2,-2,-2,
     0, 0, 0, 0, 0, 0, 0, 0,
     2, 2, 2, 2, 2, 2, 2, 2,
    -4,-4, 4, 4,-4,-4, 4, 4,
    -4, 4,-2, 0, 2, 0, 0, 0};
// A-load offsets per slot (dy*40+dx for real taps; pads chosen to complete
// the bank set; all resulting addresses stay inside the 640-float tile)
__constant__ short c_toff[72] = {
    -123,-83,-43,-3, 37, 77,117, 29,
    -121,-81,-41,-1, 39, 79,119, 31,
    -119,-79,-39, 1, 41, 81,121, 33,
    -117,-77,-37, 3, 43, 83,123, 35,
    -162,-122,-82,-42,-2, 38, 78,118,
    -160,-120,-80,-40, 0, 40, 80,120,
    -158,-118,-78,-38, 2, 42, 82,122,
    -164,-84,-156,-76,-4, 76,  4, 84,
     156,164,158,160,162, 10, 18, 26};

__device__ __forceinline__ uint32_t cvt_tf32(float v){
    uint32_t r; asm("cvt.rna.tf32.f32 %0, %1;" : "=r"(r) : "f"(v)); return r;
}
__device__ __forceinline__ void mma_tf32(float* d, const uint32_t* a, uint32_t b0, uint32_t b1){
    asm volatile("mma.sync.aligned.m16n8k8.row.col.f32.tf32.tf32.f32 "
        "{%0,%1,%2,%3}, {%4,%5,%6,%7}, {%8,%9}, {%0,%1,%2,%3};"
        : "+f"(d[0]), "+f"(d[1]), "+f"(d[2]), "+f"(d[3])
        : "r"(a[0]), "r"(a[1]), "r"(a[2]), "r"(a[3]), "r"(b0), "r"(b1));
}
__device__ __forceinline__ uint32_t smem_u32(const void* p){
    uint32_t a;
    asm("{ .reg .u64 t; cvta.to.shared.u64 t, %1; cvt.u32.u64 %0, t; }" : "=r"(a) : "l"(p));
    return a;
}
__device__ __forceinline__ void cpa16(uint32_t dst, const void* src){
    asm volatile("cp.async.cg.shared.global [%0], [%1], 16;"
                 :: "r"(dst), "l"(src) : "memory");
}
#define CP_COMMIT() asm volatile("cp.async.commit_group;" ::: "memory")
#define CP_WAIT0()  asm volatile("cp.async.wait_group 0;" ::: "memory")

// ---------------- kernel 1: edge softmax ----------------
__global__ void k_softmax(const float* __restrict__ arch, const float* __restrict__ norms){
    int e = threadIdx.x;
    if (e >= EDGES) return;
    int node = c_edge_node[e], i = c_edge_i[e];
    float nrm = fmaxf(norms[node*(NODES+1)+i], 1e-5f);
    const float* a = arch + (size_t)(node*(NODES+1)+i)*12;
    float l[12], mx = -1e30f;
    #pragma unroll
    for (int k = 0; k < 12; k++){ l[k] = a[k] / nrm; mx = fmaxf(mx, l[k]); }
    float s = 0.f;
    #pragma unroll
    for (int k = 0; k < 12; k++){ l[k] = expf(l[k] - mx); s += l[k]; }
    float inv = 1.f / s;
    #pragma unroll
    for (int k = 0; k < 12; k++) g_w[e][k] = l[k] * inv;
}

// ---------------- kernel 2: merge ops into tf32 B tiles ----------------
__global__ void k_mergeB(const float* __restrict__ w3c,  const float* __restrict__ w5c,
                         const float* __restrict__ w7c,  const float* __restrict__ w1c,
                         const float* __restrict__ s3dw, const float* __restrict__ s3pw,
                         const float* __restrict__ s5dw, const float* __restrict__ s5pw,
                         const float* __restrict__ d3c,  const float* __restrict__ d5c){
    long long t = (long long)blockIdx.x * blockDim.x + threadIdx.x;
    const long long TOT = (long long)EDGES * 64 * 64 * 72;
    if (t >= TOT) return;
    int s   = (int)(t % 72);           // slot index
    long long r1 = t / 72;
    int o   = (int)(r1 & 63);
    long long r2 = r1 >> 6;
    int i   = (int)(r2 & 63);
    int e   = (int)(r2 >> 6);
    float val = 0.f;
    int dy = c_sdy[s], dx = c_sdx[s];
    if (dy != 99){
        int ady = dy < 0 ? -dy : dy;
        int adx = dx < 0 ? -dx : dx;
        const float* w = g_w[e];
        long long oi = ((long long)e*64 + o)*64 + i;
        long long ei = (long long)e*64 + i;
        if (ady <= 3 && adx <= 3)
            val += w[3] * w7c[oi*49 + (dy+3)*7 + (dx+3)];
        if (ady <= 2 && adx <= 2){
            val += w[2] * w5c[oi*25 + (dy+2)*5 + (dx+2)];
            val += w[8] * s5pw[oi] * s5dw[ei*25 + (dy+2)*5 + (dx+2)];
        }
        if (ady <= 1 && adx <= 1){
            val += w[1] * w3c[oi*9 + (dy+1)*3 + (dx+1)];
            val += w[7] * s3pw[oi] * s3dw[ei*9 + (dy+1)*3 + (dx+1)];
        }
        if (dy == 0 && dx == 0){
            val += w[4] * w1c[oi];
            if (o == i) val += w[0];
        }
        if (((dy & 1) == 0) && ((dx & 1) == 0)){
            if (ady <= 2 && adx <= 2)
                val += w[9] * d3c[oi*9 + (dy/2+1)*3 + (dx/2+1)];
            val += w[10] * d5c[oi*25 + (dy/2+2)*5 + (dx/2+2)];
        }
    }
    // pair-interleave within each 8-group: idx<4 -> 2*idx ; idx>=4 -> 2*(idx-4)+1
    int kc = s >> 3, idx = s & 7;
    int pos = kc*8 + ((idx < 4) ? (idx*2) : ((idx-4)*2 + 1));
    g_Bk[r1*72 + pos] = __uint_as_float(cvt_tf32(val));
}

// ---------------- kernel 3: max/avg pooling accumulate ----------------
template<bool INIT>
__global__ void k_pool(const float* __restrict__ xin, float* __restrict__ dout,
                       int e, int src_sel, int dst_sel){
    const float* src = (src_sel == 0) ? xin : g_state[src_sel - 1];
    float* dst = (dst_sel == 3) ? dout : g_state[dst_sel];
    size_t base = (size_t)blockIdx.x * PLANE;
    __shared__ float tile[PLANE];
    for (int t = threadIdx.x; t < PLANE; t += 256) tile[t] = src[base + t];
    float w5v = g_w[e][5], w6v = g_w[e][6];
    __syncthreads();
    #pragma unroll
    for (int q = 0; q < 4; q++){
        int p = threadIdx.x + q*256;
        int y = p >> 5, x = p & 31;
        float m = -INFINITY, s = 0.f;
        #pragma unroll
        for (int dy = -1; dy <= 1; dy++){
            int yy = y + dy;
            if (yy < 0 || yy >= HWD) continue;
            #pragma unroll
            for (int dx = -1; dx <= 1; dx++){
                int xx = x + dx;
                if (xx < 0 || xx >= HWD) continue;
                float v = tile[yy*HWD + xx];
                m = fmaxf(m, v);
                s += v;
            }
        }
        float r = w5v*m + w6v*(s * (1.f/9.f));
        if (INIT) dst[base + p] = r;
        else      dst[base + p] += r;
    }
}

// ---------------- kernel 4: tf32 mma.sync implicit-GEMM, conflict-free smem ----------------
// CTA = 8 image rows x 64 oc. Warp = one row (two m16 frags) x 64 oc.
// Double-buffered plane + B; staging via 16B cp.async (halo zeroed once);
// column-grouped taps -> conflict-free A LDS; stride-72 B -> conflict-free LDS.64.
__global__ __launch_bounds__(256)
void k_mma(const float* __restrict__ xin, float* __restrict__ dout,
           const int* __restrict__ idx_all, int e, int src_sel, int dst_sel){
    const float* src = (src_sel == 0) ? xin : g_state[src_sel - 1];
    float* dst = (dst_sel == 3) ? dout : g_state[dst_sel];

    __shared__ float pl[2][640];       // rows R0-4..R0+11, cols -4..35 (halo zero)
    __shared__ float Bs[2][64*72];     // [oc][72], natural stride
    __shared__ int   ids_s[64];
    __shared__ short toff_s[72];

    int n   = blockIdx.y;
    int R0  = blockIdx.x * 8;
    int tid = threadIdx.x;
    int lane = tid & 31;
    int w    = tid >> 5;

    if (tid < 64) ids_s[tid] = idx_all[e*64 + tid];
    if (tid < 72) toff_s[tid] = c_toff[tid];

    // zero both plane buffers once (halo + off-image rows stay zero)
    #pragma unroll
    for (int t = 0; t < 3; t++){
        int u = tid + t*256;
        if (u < 640){ pl[0][u] = 0.f; pl[1][u] = 0.f; }
    }

    // unified staging descriptors: 5 cp.async16 per thread
    // tasks 0..127  -> plane (row = v>>3, qcol = v&7), valid rows only
    // tasks 128..1279 -> B word (v-128)*4 floats, straight copy
    uint32_t s_dst[5]; int s_src[5]; bool s_isB[5]; bool s_on[5];
    #pragma unroll
    for (int t = 0; t < 5; t++){
        int v = tid + t*256;
        if (v < 128){
            int r = v >> 3, q = v & 7;
            int gy = R0 - 4 + r;
            s_isB[t] = false;
            s_on[t]  = (gy >= 0 && gy < HWD);
            s_dst[t] = (r*40 + 4 + q*4) * 4;          // byte offset in pl buffer
            s_src[t] = gy*HWD + q*4;                   // float offset in plane
        } else {
            int u = v - 128;
            s_isB[t] = true;
            s_on[t]  = true;
            s_dst[t] = u * 16;                          // byte offset in Bs buffer
            s_src[t] = u * 4;                           // float offset in B tile
        }
    }
    uint32_t plb[2] = { smem_u32(&pl[0][0]), smem_u32(&pl[1][0]) };
    uint32_t bsb[2] = { smem_u32(&Bs[0][0]), smem_u32(&Bs[1][0]) };
    const float* bkbase = g_Bk + (size_t)e*64*64*72;
    size_t nbase = (size_t)n*CCH*PLANE;
    __syncthreads();   // ids_s + zeroed tiles ready

    // prologue: stage ci=0 into buffer 0
    {
        const float* sp = src + nbase + (size_t)ids_s[0]*PLANE;
        #pragma unroll
        for (int t = 0; t < 5; t++){
            if (!s_on[t]) continue;
            if (s_isB[t]) cpa16(bsb[0] + s_dst[t], bkbase + s_src[t]);
            else          cpa16(plb[0] + s_dst[t], sp + s_src[t]);
        }
        CP_COMMIT();
        CP_WAIT0();
    }
    __syncthreads();

    float acc[2][8][4];
    #pragma unroll
    for (int f = 0; f < 2; f++)
        #pragma unroll
        for (int nf = 0; nf < 8; nf++)
            #pragma unroll
            for (int q = 0; q < 4; q++) acc[f][nf][q] = 0.f;

    int pbase = (w + 4)*40 + 4 + (lane >> 2);

    for (int ci = 0; ci < 64; ci++){
        int cur = ci & 1;
        if (ci < 63){
            const float* sp = src + nbase + (size_t)ids_s[ci+1]*PLANE;
            const float* bp = bkbase + (size_t)(ci+1)*4608;
            #pragma unroll
            for (int t = 0; t < 5; t++){
                if (!s_on[t]) continue;
                if (s_isB[t]) cpa16(bsb[cur^1] + s_dst[t], bp + s_src[t]);
                else          cpa16(plb[cur^1] + s_dst[t], sp + s_src[t]);
            }
            CP_COMMIT();
        }

        const float* plc = pl[cur];
        const float* bsc = Bs[cur];
        #pragma unroll
        for (int kc = 0; kc < 9; kc++){
            int o0 = toff_s[kc*8 + (lane & 3)];
            int o1 = toff_s[kc*8 + 4 + (lane & 3)];
            uint32_t a[2][4];
            #pragma unroll
            for (int f = 0; f < 2; f++){
                int pb = pbase + f*16;
                a[f][0] = cvt_tf32(plc[pb + o0]);
                a[f][1] = cvt_tf32(plc[pb + 8 + o0]);
                a[f][2] = cvt_tf32(plc[pb + o1]);
                a[f][3] = cvt_tf32(plc[pb + 8 + o1]);
            }
            #pragma unroll
            for (int nf = 0; nf < 8; nf++){
                int bi = (nf*8 + (lane >> 2))*72 + kc*8 + (lane & 3)*2;
                float2 bb = *(const float2*)(bsc + bi);
                uint32_t b0 = __float_as_uint(bb.x);
                uint32_t b1 = __float_as_uint(bb.y);
                mma_tf32(acc[0][nf], a[0], b0, b1);
                mma_tf32(acc[1][nf], a[1], b0, b1);
            }
        }
        CP_WAIT0();
        __syncthreads();
    }

    // epilogue: scatter-add. D frag (m16n8): rows lane>>2 (+8), cols 2*(lane&3)+{0,1}
    int y = R0 + w;
    size_t nb = nbase + (size_t)y*HWD;
    #pragma unroll
    for (int f = 0; f < 2; f++){
        int x0 = f*16 + (lane >> 2);
        #pragma unroll
        for (int nf = 0; nf < 8; nf++){
            int oc = nf*8 + 2*(lane & 3);
            size_t p0 = nb + (size_t)ids_s[oc]*PLANE;
            size_t p1 = nb + (size_t)ids_s[oc+1]*PLANE;
            dst[p0 + x0]     += acc[f][nf][0];
            dst[p1 + x0]     += acc[f][nf][1];
            dst[p0 + x0 + 8] += acc[f][nf][2];
            dst[p1 + x0 + 8] += acc[f][nf][3];
        }
    }
}

// ---------------- launch ----------------
extern "C" void kernel_launch(void* const* d_in, const int* in_sizes, int n_in,
                              void* d_out, int out_size){
    const float* x     = (const float*)d_in[0];
    const float* arch  = (const float*)d_in[1];
    const float* norms = (const float*)d_in[2];
    const int*   idx   = (const int*)  d_in[3];
    const float* w3c   = (const float*)d_in[4];
    const float* w5c   = (const float*)d_in[5];
    const float* w7c   = (const float*)d_in[6];
    const float* w1c   = (const float*)d_in[7];
    const float* s3dw  = (const float*)d_in[8];
    const float* s3pw  = (const float*)d_in[9];
    const float* s5dw  = (const float*)d_in[10];
    const float* s5pw  = (const float*)d_in[11];
    const float* d3c   = (const float*)d_in[12];
    const float* d5c   = (const float*)d_in[13];
    float* out = (float*)d_out;

    k_softmax<<<1, 32>>>(arch, norms);

    long long TOT = (long long)EDGES * 64 * 64 * 72;
    int mb = (int)((TOT + 255) / 256);
    k_mergeB<<<mb, 256>>>(w3c, w5c, w7c, w1c, s3dw, s3pw, s5dw, s5pw, d3c, d5c);

    int e = 0;
    for (int node = 0; node < NODES; node++){
        for (int i = 0; i <= node; i++){
            if (i == 0) k_pool<true ><<<NB*CCH, 256>>>(x, out, e, i, node);
            else        k_pool<false><<<NB*CCH, 256>>>(x, out, e, i, node);
            k_mma<<<dim3(4, NB), 256>>>(x, out, idx, e, i, node);
            e++;
        }
    }
}